// round 15
// baseline (speedup 1.0000x reference)
#include <cuda_runtime.h>
#include <cuda_bf16.h>
#include <cuda_fp16.h>
#include <stdint.h>

// H3TCSNetwork, mma.sync path. R15 = R14 with ONE continuous per-warp B stream:
// weights repacked warp-contiguous (3 hidden + 11 head blocks per warp),
// depth-8 cp.async ring staged once at kernel start (prologue hidden behind
// layer-0 FFMA), fully-unrolled 16-kstep bodies (slot addrs compile-time).

#define NTHREADS 256
#define MROWS    64
#define HID      256
#define NOUT     2695
#define APITCH   264                  // fp16 elems per smem plane row (528 B)

// g_pack2: 112 blocks of 2048 uint2 (16 ksteps x 1KB). Block (w*14+j):
//   j<3  -> hidden layer j, cols w*32..w*32+31
//   j>=3 -> head chunk nc=j-3, cols nc*256 + w*32 .. +31  (padded cols zero)
#define PACK2_N   (112 * 2048)

__device__ uint2 g_pack2[PACK2_N];

// ---------------- helpers ----------------
__device__ __forceinline__ uint32_t smem_u32(const void* p){
    return (uint32_t)__cvta_generic_to_shared(p);
}
__device__ __forceinline__ uint32_t pack2h(float lo, float hi){
    uint32_t r;
    asm("cvt.rn.f16x2.f32 %0, %1, %2;" : "=r"(r) : "f"(hi), "f"(lo));
    return r;
}
__device__ __forceinline__ float silu_f(float v){
    return __fdividef(v, 1.0f + __expf(-v));
}
__device__ __forceinline__ void ldsm_x4(uint32_t a[4], uint32_t addr){
    asm volatile("ldmatrix.sync.aligned.m8n8.x4.shared.b16 {%0,%1,%2,%3}, [%4];"
                 : "=r"(a[0]), "=r"(a[1]), "=r"(a[2]), "=r"(a[3]) : "r"(addr));
}
__device__ __forceinline__ void mma_f16(float c[4], const uint32_t a[4],
                                        uint32_t b0, uint32_t b1){
    asm volatile("mma.sync.aligned.m16n8k16.row.col.f32.f16.f16.f32 "
                 "{%0,%1,%2,%3}, {%4,%5,%6,%7}, {%8,%9}, {%0,%1,%2,%3};"
                 : "+f"(c[0]), "+f"(c[1]), "+f"(c[2]), "+f"(c[3])
                 : "r"(a[0]), "r"(a[1]), "r"(a[2]), "r"(a[3]), "r"(b0), "r"(b1));
}
__device__ __forceinline__ void cp16(uint32_t dst, const void* src){
    asm volatile("cp.async.ca.shared.global [%0], [%1], 16;" :: "r"(dst), "l"(src));
}
#define CPC()  asm volatile("cp.async.commit_group;" ::: "memory")
#define CPW6() asm volatile("cp.async.wait_group 6;" ::: "memory")
__device__ __forceinline__ void lds128(uint4& v, uint32_t addr){
    asm volatile("ld.shared.v4.u32 {%0,%1,%2,%3}, [%4];"
                 : "=r"(v.x), "=r"(v.y), "=r"(v.z), "=r"(v.w) : "r"(addr));
}

// ---------------- weight pack kernel ----------------
__global__ void pack_weights(const float* __restrict__ W1, const float* __restrict__ W2,
                             const float* __restrict__ W3, const float* __restrict__ Wh)
{
    int idx = blockIdx.x * blockDim.x + threadIdx.x;
    if (idx >= PACK2_N) return;
    int blk = idx >> 11;
    int w   = blk / 14;
    int j   = blk % 14;
    int rem = idx & 2047;
    int s   = rem >> 7;
    int pos = rem & 127;
    int L, nt;
    if (pos < 64){ L = pos >> 1; nt = pos & 1; }
    else         { L = (pos - 64) >> 1; nt = 2 + ((pos - 64) & 1); }
    int q  = L & 3;
    int nl = L >> 2;
    int k0 = s * 16 + q * 2;
    int n_local = nt * 8 + nl;

    const float* W; int N; int n;
    if (j < 3){
        W = (j == 0) ? W1 : (j == 1) ? W2 : W3;
        N = HID;
        n = w * 32 + n_local;
    } else {
        W = Wh; N = NOUT;
        n = (j - 3) * 256 + w * 32 + n_local;
    }
    uint2 v = make_uint2(0, 0);
    if (n < N){
        v.x = pack2h(W[(size_t)k0     * N + n], W[(size_t)(k0+1) * N + n]);
        v.y = pack2h(W[(size_t)(k0+8) * N + n], W[(size_t)(k0+9) * N + n]);
    }
    g_pack2[idx] = v;
}

#define MMA4(accrow, a, bA, bB) \
    do { \
        mma_f16((accrow)[0], a, (bA).x, (bA).y); \
        mma_f16((accrow)[1], a, (bA).z, (bA).w); \
        mma_f16((accrow)[2], a, (bB).x, (bB).y); \
        mma_f16((accrow)[3], a, (bB).z, (bB).w); \
    } while(0)

#define RING_WARP 8192u      // 8 slots x 1024B per warp

// ------- 16-kstep GEMM body (fp16 1-term, 64x32 tile), continuous ring ------
// Fully unrolled: slot addresses compile-time. Commits 1 group per kstep.
// NORMAL stages all 16 next-blocks; LAST stages only s<9 (stream end).
template<bool LAST>
__device__ __forceinline__ void gemm16(uint32_t abase, uint32_t bring, uint32_t L16,
                                       const char*& src, float acc[4][4][4])
{
    const uint32_t MT = 16u*(APITCH*2);
    uint32_t a0[4], a1[4];
    ldsm_x4(a0, abase);                        // mt0, kstep 0
    #pragma unroll
    for (int s = 0; s < 16; s++){
        CPW6();                                // slot for kstep s complete
        const uint32_t sa = bring + (uint32_t)(s & 7)*1024u + L16;
        uint4 bA, bB;
        lds128(bA, sa);
        lds128(bB, sa + 512u);

        const uint32_t bs = abase + (uint32_t)s * 32u;
        ldsm_x4(a1, bs + MT);                  // mt1
        MMA4(acc[0], a0, bA, bB);
        ldsm_x4(a0, bs + 2*MT);                // mt2
        MMA4(acc[1], a1, bA, bB);
        ldsm_x4(a1, bs + 3*MT);                // mt3
        MMA4(acc[2], a0, bA, bB);
        ldsm_x4(a0, bs + 32u);                 // mt0 of next kstep (pad-safe)
        MMA4(acc[3], a1, bA, bB);

        if (!LAST || s < 9){                   // stage kstep s+7 of the stream
            const uint32_t da = bring + (uint32_t)((s + 7) & 7)*1024u + L16;
            cp16(da,        src + L16);
            cp16(da + 512u, src + 512u + L16);
            src += 1024;
        }
        CPC();                                 // one group per kstep (may be empty)
    }
}

__device__ __forceinline__ float hsel(int col, float l, float r, float n){
    if (col < 1225) return 1.0f;
    if (col < 1715) return l;
    if (col < 2205) return r;
    return n;
}

#define ACC_CLEAR(acc) \
    do { _Pragma("unroll") for (int a_ = 0; a_ < 4; a_++) \
         _Pragma("unroll") for (int b_ = 0; b_ < 4; b_++) \
         _Pragma("unroll") for (int c_ = 0; c_ < 4; c_++) (acc)[a_][b_][c_] = 0.0f; } while(0)

// ---------------- main fused kernel ----------------
__global__ __launch_bounds__(NTHREADS, 2)
void h3tcs_mma_kernel(const float* __restrict__ x,
                      const float* __restrict__ W0, const float* __restrict__ b0,
                      const float* __restrict__ b1, const float* __restrict__ b2,
                      const float* __restrict__ b3, const float* __restrict__ bh,
                      float* __restrict__ out)
{
    extern __shared__ char smem[];
    char*   ringc = smem;                             // 8 warps * 8KB = 64KB
    __half* pA    = (__half*)(smem + 8*RING_WARP);    // fp16 activation plane
    float* xs     = (float*)(pA + MROWS*APITCH);
    float* scl    = xs  + MROWS*7;
    float* scr    = scl + MROWS;
    float* scn    = scr + MROWS;
    float* bias_s = scn + MROWS;                      // 3*256

    const int tid  = threadIdx.x;
    const int lane = tid & 31;
    const int wid  = tid >> 5;
    const int r0   = blockIdx.x * MROWS;
    const uint32_t bring = smem_u32(ringc) + (uint32_t)wid * RING_WARP;
    const uint32_t L16   = (uint32_t)lane * 16u;

    // ---- ring prologue: stage first 7 ksteps of this warp's 224-kstep stream
    const char* src = (const char*)(g_pack2 + (size_t)wid * 14 * 2048);
    #pragma unroll
    for (int i = 0; i < 7; i++){
        cp16(bring + (uint32_t)i*1024u + L16,        src + L16);
        cp16(bring + (uint32_t)i*1024u + 512u + L16, src + 512u + L16);
        CPC();
        src += 1024;
    }

    for (int i = tid; i < MROWS*7; i += NTHREADS) xs[i] = x[(size_t)r0*7 + i];
    bias_s[tid]       = b1[tid];
    bias_s[256 + tid] = b2[tid];
    bias_s[512 + tid] = b3[tid];
    __syncthreads();

    if (tid < MROWS){
        float lam = xs[tid*7];
        float s = 1.0f / (1.0f + __expf(lam * (-5.0f/0.15f)));
        scl[tid] = 1.0f - s;
        scr[tid] = s;
        float t = lam * 5.0f;
        scn[tid] = __expf(-t*t);
    }

    // ---- layer 0 (7 -> 256), fp32 FFMA, fp16 store (covers ring prologue) ---
    {
        int j = tid;
        float w0r[7];
        #pragma unroll
        for (int k = 0; k < 7; k++) w0r[k] = W0[k*HID + j];
        float bj = b0[j];
        for (int r = 0; r < MROWS; r++){
            float v = bj;
            #pragma unroll
            for (int k = 0; k < 7; k++) v = fmaf(xs[r*7 + k], w0r[k], v);
            pA[r*APITCH + j] = __float2half(silu_f(v));
        }
    }
    __syncthreads();

    const int sub = lane >> 3;
    const int rowin = (lane & 7) + (sub & 1) * 8;
    const int colin = (sub >> 1) * 8;
    const uint32_t abase = smem_u32(pA) + ((uint32_t)rowin * APITCH + colin) * 2;

    // ---- hidden layers 1..3: fp16 1-term, m64n32 per warp ----
    #pragma unroll 1
    for (int L = 0; L < 3; L++){
        float acc[4][4][4];
        ACC_CLEAR(acc);
        gemm16<false>(abase, bring, L16, src, acc);

        __syncthreads();            // all warps done READING plane
        const float* bs = bias_s + L*256;
        #pragma unroll
        for (int mt = 0; mt < 4; mt++){
            int rb = mt*16 + (lane >> 2);
            #pragma unroll
            for (int nt = 0; nt < 4; nt++){
                int cb = wid*32 + nt*8 + (lane & 3)*2;
                float bb0 = bs[cb], bb1 = bs[cb+1];
                float v0 = silu_f(acc[mt][nt][0] + bb0);
                float v1 = silu_f(acc[mt][nt][1] + bb1);
                *(uint32_t*)&pA[rb*APITCH + cb] = pack2h(v0, v1);
                float v2 = silu_f(acc[mt][nt][2] + bb0);
                float v3 = silu_f(acc[mt][nt][3] + bb1);
                *(uint32_t*)&pA[(rb+8)*APITCH + cb] = pack2h(v2, v3);
            }
        }
        __syncthreads();            // plane fully rewritten
    }

    // ---- head (256 -> 2695 padded 2816), fp16 1-term ----
    #pragma unroll 1
    for (int nc = 0; nc < 11; nc++){
        float acc[4][4][4];
        ACC_CLEAR(acc);
        if (nc < 10) gemm16<false>(abase, bring, L16, src, acc);
        else         gemm16<true >(abase, bring, L16, src, acc);

        int nbase = nc*256 + wid*32;
        #pragma unroll
        for (int mt = 0; mt < 4; mt++){
            int rr = mt*16 + (lane >> 2);
            float l0 = scl[rr],   rv0 = scr[rr],   n0s = scn[rr];
            float l1 = scl[rr+8], rv1 = scr[rr+8], n1s = scn[rr+8];
            #pragma unroll
            for (int nt = 0; nt < 4; nt++){
                int cb = nbase + nt*8 + (lane & 3)*2;
                if (cb < NOUT){
                    float bb0 = __ldg(&bh[cb]);
                    float s0 = hsel(cb, l0, rv0, n0s);
                    float s1 = hsel(cb, l1, rv1, n1s);
                    out[(size_t)(r0+rr)   * NOUT + cb] = (acc[mt][nt][0] + bb0) * s0;
                    out[(size_t)(r0+rr+8) * NOUT + cb] = (acc[mt][nt][2] + bb0) * s1;
                    if (cb + 1 < NOUT){
                        float bb1 = __ldg(&bh[cb+1]);
                        float t0 = hsel(cb+1, l0, rv0, n0s);
                        float t1 = hsel(cb+1, l1, rv1, n1s);
                        out[(size_t)(r0+rr)   * NOUT + cb+1] = (acc[mt][nt][1] + bb1) * t0;
                        out[(size_t)(r0+rr+8) * NOUT + cb+1] = (acc[mt][nt][3] + bb1) * t1;
                    }
                }
            }
        }
    }
}

// ---------------- launch ----------------
#define SMEM_BYTES (8*RING_WARP + MROWS*APITCH*2 + (MROWS*7 + 3*MROWS + 3*256)*4)

extern "C" void kernel_launch(void* const* d_in, const int* in_sizes, int n_in,
                              void* d_out, int out_size)
{
    const float* x  = (const float*)d_in[0];
    const float* W0 = (const float*)d_in[1];
    const float* b0 = (const float*)d_in[2];
    const float* W1 = (const float*)d_in[3];
    const float* b1 = (const float*)d_in[4];
    const float* W2 = (const float*)d_in[5];
    const float* b2 = (const float*)d_in[6];
    const float* W3 = (const float*)d_in[7];
    const float* b3 = (const float*)d_in[8];
    const float* Wh = (const float*)d_in[9];
    const float* bh = (const float*)d_in[10];
    float* out = (float*)d_out;

    int B = in_sizes[0] / 7;

    cudaFuncSetAttribute(h3tcs_mma_kernel,
                         cudaFuncAttributeMaxDynamicSharedMemorySize, SMEM_BYTES);

    pack_weights<<<(PACK2_N + 255)/256, 256>>>(W1, W2, W3, Wh);
    h3tcs_mma_kernel<<<B / MROWS, NTHREADS, SMEM_BYTES>>>(x, W0, b0, b1, b2, b3, bh, out);
}

// round 16
// speedup vs baseline: 1.0343x; 1.0343x over previous
#include <cuda_runtime.h>
#include <cuda_bf16.h>
#include <cuda_fp16.h>
#include <stdint.h>

// H3TCSNetwork, mma.sync path. R16 = R14 (580us) with:
//  - ring depth 8 (power-of-2 slot addressing, no mod-6 bookkeeping)
//  - wait distance 5 ksteps (prologue 6 slots)
//  - k-loop unroll 2 (body stays inside L0 I$; R15 showed full unroll thrashes)

#define NTHREADS 256
#define MROWS    64
#define HID      256
#define NOUT     2695
#define APITCH   264                  // fp16 elems per smem plane row (528 B)

// packed layout: per (gemm,32-col chunk): 16 ksteps x 128 uint2 (1KB/kstep)
// chunk-blocks: 24 hidden (3 gemms x 8) + 88 head (2816/32) = 112
#define CB_HEAD0  24
#define PACK2_N   (112 * 2048)        // uint2 count = 229376 (1.75 MB)

__device__ uint2 g_pack2[PACK2_N];

// ---------------- helpers ----------------
__device__ __forceinline__ uint32_t smem_u32(const void* p){
    return (uint32_t)__cvta_generic_to_shared(p);
}
__device__ __forceinline__ uint32_t pack2h(float lo, float hi){
    uint32_t r;
    asm("cvt.rn.f16x2.f32 %0, %1, %2;" : "=r"(r) : "f"(hi), "f"(lo));
    return r;
}
__device__ __forceinline__ float silu_f(float v){
    return __fdividef(v, 1.0f + __expf(-v));
}
__device__ __forceinline__ void ldsm_x4(uint32_t a[4], uint32_t addr){
    asm volatile("ldmatrix.sync.aligned.m8n8.x4.shared.b16 {%0,%1,%2,%3}, [%4];"
                 : "=r"(a[0]), "=r"(a[1]), "=r"(a[2]), "=r"(a[3]) : "r"(addr));
}
__device__ __forceinline__ void mma_f16(float c[4], const uint32_t a[4],
                                        uint32_t b0, uint32_t b1){
    asm volatile("mma.sync.aligned.m16n8k16.row.col.f32.f16.f16.f32 "
                 "{%0,%1,%2,%3}, {%4,%5,%6,%7}, {%8,%9}, {%0,%1,%2,%3};"
                 : "+f"(c[0]), "+f"(c[1]), "+f"(c[2]), "+f"(c[3])
                 : "r"(a[0]), "r"(a[1]), "r"(a[2]), "r"(a[3]), "r"(b0), "r"(b1));
}
__device__ __forceinline__ void cp16(uint32_t dst, const void* src){
    asm volatile("cp.async.ca.shared.global [%0], [%1], 16;" :: "r"(dst), "l"(src));
}
#define CPC()  asm volatile("cp.async.commit_group;" ::: "memory")
#define CPW5() asm volatile("cp.async.wait_group 5;" ::: "memory")
__device__ __forceinline__ void lds128(uint4& v, uint32_t addr){
    asm volatile("ld.shared.v4.u32 {%0,%1,%2,%3}, [%4];"
                 : "=r"(v.x), "=r"(v.y), "=r"(v.z), "=r"(v.w) : "r"(addr));
}

// ---------------- weight pack kernel ----------------
// uint2 idx decode: cb = idx>>11; rem = idx&2047; s = rem>>7; pos = rem&127.
//   pos<64 : L = pos>>1, nt = pos&1
//   pos>=64: L = (pos-64)>>1, nt = 2 + ((pos-64)&1)
// q = L&3, nl = L>>2, k0 = s*16 + q*2, n = chunk*32 + nt*8 + nl.
__global__ void pack_weights(const float* __restrict__ W1, const float* __restrict__ W2,
                             const float* __restrict__ W3, const float* __restrict__ Wh)
{
    int idx = blockIdx.x * blockDim.x + threadIdx.x;
    if (idx >= PACK2_N) return;
    int cb  = idx >> 11;
    int rem = idx & 2047;
    int s   = rem >> 7;
    int pos = rem & 127;
    int L, nt;
    if (pos < 64){ L = pos >> 1; nt = pos & 1; }
    else         { L = (pos - 64) >> 1; nt = 2 + ((pos - 64) & 1); }
    int q  = L & 3;
    int nl = L >> 2;
    int k0 = s * 16 + q * 2;
    int n_local = nt * 8 + nl;

    const float* W; int N; int n;
    if (cb < CB_HEAD0){
        int g = cb >> 3;
        W = (g == 0) ? W1 : (g == 1) ? W2 : W3;
        N = HID;
        n = (cb & 7) * 32 + n_local;
    } else {
        W = Wh; N = NOUT;
        n = (cb - CB_HEAD0) * 32 + n_local;
    }
    uint2 v = make_uint2(0, 0);
    if (n < N){
        v.x = pack2h(W[(size_t)k0     * N + n], W[(size_t)(k0+1) * N + n]);
        v.y = pack2h(W[(size_t)(k0+8) * N + n], W[(size_t)(k0+9) * N + n]);
    }
    g_pack2[idx] = v;
}

#define MMA4(accrow, a, bA, bB) \
    do { \
        mma_f16((accrow)[0], a, (bA).x, (bA).y); \
        mma_f16((accrow)[1], a, (bA).z, (bA).w); \
        mma_f16((accrow)[2], a, (bB).x, (bB).y); \
        mma_f16((accrow)[3], a, (bB).z, (bB).w); \
    } while(0)

#define RING_WARP 8192u      // 8 slots x 1024B per warp

// ------- warp GEMM: fp16 1-term, 64x32 tile, cp.async ring depth 8 ----------
// Prologue commits slots 0..5; body kstep s: wait_group 5 (completes slot s),
// read slot s&7, MMA (A-pipelined), stage slot (s+6)&7, commit. Distance 5.
__device__ __forceinline__ void warp_gemm_cp(uint32_t abase, uint32_t bring,
                                             int cb, int lane, float acc[4][4][4])
{
    const char* src = (const char*)(g_pack2 + (size_t)cb * 2048);
    const uint32_t L16 = (uint32_t)lane * 16u;

    #pragma unroll
    for (int i = 0; i < 6; i++){
        cp16(bring + (uint32_t)i*1024u + L16,        src + L16);
        cp16(bring + (uint32_t)i*1024u + 512u + L16, src + 512u + L16);
        CPC();
        src += 1024;
    }

    const uint32_t MT = 16u*(APITCH*2);
    uint32_t a0[4], a1[4];
    ldsm_x4(a0, abase);                        // mt0, kstep 0

    #pragma unroll 2
    for (int s = 0; s < 16; s++){
        CPW5();                                // slot s complete
        const uint32_t sa = bring + (uint32_t)(s & 7)*1024u + L16;
        uint4 bA, bB;
        lds128(bA, sa);
        lds128(bB, sa + 512u);

        const uint32_t bs = abase + (uint32_t)s * 32u;
        ldsm_x4(a1, bs + MT);                  // mt1
        MMA4(acc[0], a0, bA, bB);
        ldsm_x4(a0, bs + 2*MT);                // mt2
        MMA4(acc[1], a1, bA, bB);
        ldsm_x4(a1, bs + 3*MT);                // mt3
        MMA4(acc[2], a0, bA, bB);
        ldsm_x4(a0, bs + 32u);                 // mt0, kstep s+1 (s=15: row pad, in-plane)
        MMA4(acc[3], a1, bA, bB);

        if (s < 10){                           // stage kstep s+6
            const uint32_t da = bring + (uint32_t)((s + 6) & 7)*1024u + L16;
            cp16(da,        src + L16);
            cp16(da + 512u, src + 512u + L16);
            src += 1024;
        }
        CPC();                                 // commit (possibly empty) every kstep
    }
}

__device__ __forceinline__ float hsel(int col, float l, float r, float n){
    if (col < 1225) return 1.0f;
    if (col < 1715) return l;
    if (col < 2205) return r;
    return n;
}

// ---------------- main fused kernel ----------------
__global__ __launch_bounds__(NTHREADS, 2)
void h3tcs_mma_kernel(const float* __restrict__ x,
                      const float* __restrict__ W0, const float* __restrict__ b0,
                      const float* __restrict__ b1, const float* __restrict__ b2,
                      const float* __restrict__ b3, const float* __restrict__ bh,
                      float* __restrict__ out)
{
    extern __shared__ char smem[];
    char*   ringc = smem;                             // 8 warps * 8KB = 64KB
    __half* pA    = (__half*)(smem + 8*RING_WARP);    // fp16 activation plane
    float* xs     = (float*)(pA + MROWS*APITCH);
    float* scl    = xs  + MROWS*7;
    float* scr    = scl + MROWS;
    float* scn    = scr + MROWS;
    float* bias_s = scn + MROWS;                      // 3*256
    float* bias_h = bias_s + 3*256;                   // 2696

    const int tid  = threadIdx.x;
    const int lane = tid & 31;
    const int wid  = tid >> 5;
    const int r0   = blockIdx.x * MROWS;
    const uint32_t bring = smem_u32(ringc) + (uint32_t)wid * RING_WARP;

    for (int i = tid; i < MROWS*7; i += NTHREADS) xs[i] = x[(size_t)r0*7 + i];
    bias_s[tid]       = b1[tid];
    bias_s[256 + tid] = b2[tid];
    bias_s[512 + tid] = b3[tid];
    for (int i = tid; i < NOUT; i += NTHREADS) bias_h[i] = bh[i];
    __syncthreads();

    if (tid < MROWS){
        float lam = xs[tid*7];
        float s = 1.0f / (1.0f + __expf(lam * (-5.0f/0.15f)));
        scl[tid] = 1.0f - s;
        scr[tid] = s;
        float t = lam * 5.0f;
        scn[tid] = __expf(-t*t);
    }

    // ---- layer 0 (7 -> 256), fp32 FFMA, fp16 store ----
    {
        int j = tid;
        float w0r[7];
        #pragma unroll
        for (int k = 0; k < 7; k++) w0r[k] = W0[k*HID + j];
        float bj = b0[j];
        for (int r = 0; r < MROWS; r++){
            float v = bj;
            #pragma unroll
            for (int k = 0; k < 7; k++) v = fmaf(xs[r*7 + k], w0r[k], v);
            pA[r*APITCH + j] = __float2half(silu_f(v));
        }
    }
    __syncthreads();

    const int sub = lane >> 3;
    const int rowin = (lane & 7) + (sub & 1) * 8;
    const int colin = (sub >> 1) * 8;
    const uint32_t abase = smem_u32(pA) + ((uint32_t)rowin * APITCH + colin) * 2;

    // ---- hidden layers 1..3: fp16 1-term, m64n32 per warp ----
    #pragma unroll 1
    for (int L = 0; L < 3; L++){
        float acc[4][4][4];
        #pragma unroll
        for (int a = 0; a < 4; a++)
            #pragma unroll
            for (int b = 0; b < 4; b++)
                #pragma unroll
                for (int c = 0; c < 4; c++) acc[a][b][c] = 0.0f;

        warp_gemm_cp(abase, bring, L*8 + wid, lane, acc);

        __syncthreads();            // all warps done READING plane
        const float* bs = bias_s + L*256;
        #pragma unroll
        for (int mt = 0; mt < 4; mt++){
            int rb = mt*16 + (lane >> 2);
            #pragma unroll
            for (int nt = 0; nt < 4; nt++){
                int cb = wid*32 + nt*8 + (lane & 3)*2;
                float bb0 = bs[cb], bb1 = bs[cb+1];
                float v0 = silu_f(acc[mt][nt][0] + bb0);
                float v1 = silu_f(acc[mt][nt][1] + bb1);
                *(uint32_t*)&pA[rb*APITCH + cb] = pack2h(v0, v1);
                float v2 = silu_f(acc[mt][nt][2] + bb0);
                float v3 = silu_f(acc[mt][nt][3] + bb1);
                *(uint32_t*)&pA[(rb+8)*APITCH + cb] = pack2h(v2, v3);
            }
        }
        __syncthreads();            // plane fully rewritten
    }

    // ---- head (256 -> 2695 padded 2816), fp16 1-term ----
    #pragma unroll 1
    for (int nc = 0; nc < 11; nc++){
        float acc[4][4][4];
        #pragma unroll
        for (int a = 0; a < 4; a++)
            #pragma unroll
            for (int b = 0; b < 4; b++)
                #pragma unroll
                for (int c = 0; c < 4; c++) acc[a][b][c] = 0.0f;

        warp_gemm_cp(abase, bring, CB_HEAD0 + nc*8 + wid, lane, acc);

        int nbase = nc*256 + wid*32;
        #pragma unroll
        for (int mt = 0; mt < 4; mt++){
            int rr = mt*16 + (lane >> 2);
            float l0 = scl[rr],   rv0 = scr[rr],   n0s = scn[rr];
            float l1 = scl[rr+8], rv1 = scr[rr+8], n1s = scn[rr+8];
            #pragma unroll
            for (int nt = 0; nt < 4; nt++){
                int cb = nbase + nt*8 + (lane & 3)*2;
                if (cb < NOUT){
                    float bb0 = bias_h[cb];
                    float s0 = hsel(cb, l0, rv0, n0s);
                    float s1 = hsel(cb, l1, rv1, n1s);
                    out[(size_t)(r0+rr)   * NOUT + cb] = (acc[mt][nt][0] + bb0) * s0;
                    out[(size_t)(r0+rr+8) * NOUT + cb] = (acc[mt][nt][2] + bb0) * s1;
                    if (cb + 1 < NOUT){
                        float bb1 = bias_h[cb+1];
                        float t0 = hsel(cb+1, l0, rv0, n0s);
                        float t1 = hsel(cb+1, l1, rv1, n1s);
                        out[(size_t)(r0+rr)   * NOUT + cb+1] = (acc[mt][nt][1] + bb1) * t0;
                        out[(size_t)(r0+rr+8) * NOUT + cb+1] = (acc[mt][nt][3] + bb1) * t1;
                    }
                }
            }
        }
    }
}

// ---------------- launch ----------------
#define SMEM_BYTES (8*RING_WARP + MROWS*APITCH*2 + (MROWS*7 + 3*MROWS + 3*256 + 2696)*4)

extern "C" void kernel_launch(void* const* d_in, const int* in_sizes, int n_in,
                              void* d_out, int out_size)
{
    const float* x  = (const float*)d_in[0];
    const float* W0 = (const float*)d_in[1];
    const float* b0 = (const float*)d_in[2];
    const float* W1 = (const float*)d_in[3];
    const float* b1 = (const float*)d_in[4];
    const float* W2 = (const float*)d_in[5];
    const float* b2 = (const float*)d_in[6];
    const float* W3 = (const float*)d_in[7];
    const float* b3 = (const float*)d_in[8];
    const float* Wh = (const float*)d_in[9];
    const float* bh = (const float*)d_in[10];
    float* out = (float*)d_out;

    int B = in_sizes[0] / 7;

    cudaFuncSetAttribute(h3tcs_mma_kernel,
                         cudaFuncAttributeMaxDynamicSharedMemorySize, SMEM_BYTES);

    pack_weights<<<(PACK2_N + 255)/256, 256>>>(W1, W2, W3, Wh);
    h3tcs_mma_kernel<<<B / MROWS, NTHREADS, SMEM_BYTES>>>(x, W0, b0, b1, b2, b3, bh, out);
}